// round 1
// baseline (speedup 1.0000x reference)
#include <cuda_runtime.h>

// Problem constants (fixed by the reference)
#define NN 100000
#define EC 6400000
#define ED 400000
#define HH 8
#define FIN 5
#define BN_EPS 1e-5
#define L2_EPS 1e-12f

// ---------------- scratch (static __device__, no allocs) ----------------
__device__ int2  g_ec[EC];                      // packed (src,dst) connection edges
__device__ int2  g_ed[ED];                      // packed (src,dst) destination edges
__device__ float g_cntc[NN];
__device__ float g_cntd[NN];
__device__ __align__(32) float g_acc[NN * HH];  // scatter accumulator
__device__ __align__(32) float g_h[NN * HH];    // current post-BN features
__device__ __align__(32) float g_z[NN * HH];    // h @ Wl^T of NEXT layer (scatter payload)
__device__ __align__(32) float g_y[NN * HH];    // pre-BN activations
__device__ double g_stats[5 * 16];              // per-layer [sum(8), sumsq(8)]
__device__ int    g_mode;                       // 1 = int64 edge indices, 0 = int32

// ---------------- init: zero everything ----------------
__global__ void k_init() {
    int i = blockIdx.x * blockDim.x + threadIdx.x;
    if (i < NN * HH) g_acc[i] = 0.f;
    if (i < NN) { g_cntc[i] = 0.f; g_cntd[i] = 0.f; }
    if (i < 5 * 16) g_stats[i] = 0.0;
}

// ---------------- dtype detection ----------------
// If the edge buffer holds int64 values (< 2^31), every odd 32-bit word is 0.
// If it holds int32 indices, odd words are random node ids (nonzero w.h.p.).
__global__ void k_detect(const int* __restrict__ ei) {
    int lane = threadIdx.x;
    int v = ei[2 * lane + 1];
    unsigned ball = __ballot_sync(0xffffffffu, v == 0);
    if (lane == 0) g_mode = (ball == 0xffffffffu) ? 1 : 0;
}

// ---------------- pack edges int->int2 + degree count ----------------
__global__ void k_prep(const void* __restrict__ ei, int2* __restrict__ out,
                       float* __restrict__ cnt, int E) {
    int e = blockIdx.x * blockDim.x + threadIdx.x;
    if (e >= E) return;
    int src, dst;
    if (g_mode) {
        const long long* p = (const long long*)ei;
        src = (int)p[e]; dst = (int)p[E + e];
    } else {
        const int* p = (const int*)ei;
        src = p[e]; dst = p[E + e];
    }
    out[e] = make_int2(src, dst);
    atomicAdd(&cnt[dst], 1.f);
}

// ---------------- z for layer 1: z = x @ W1l^T  (F_IN=5 -> 8) ----------------
__global__ void k_z_first(const float* __restrict__ x, const float* __restrict__ W1l) {
    __shared__ float w[HH * FIN];
    if (threadIdx.x < HH * FIN) w[threadIdx.x] = W1l[threadIdx.x];
    __syncthreads();
    int i = blockIdx.x * blockDim.x + threadIdx.x;
    if (i >= NN) return;
    float xv[FIN];
#pragma unroll
    for (int f = 0; f < FIN; f++) xv[f] = x[i * FIN + f];
#pragma unroll
    for (int h = 0; h < HH; h++) {
        float s = 0.f;
#pragma unroll
        for (int f = 0; f < FIN; f++) s += xv[f] * w[h * FIN + f];
        g_z[i * HH + h] = s;
    }
}

// ---------------- edge scatter: acc[dst] += z[src] ----------------
__global__ void k_scatter(const int2* __restrict__ edges, int E) {
    int e = blockIdx.x * blockDim.x + threadIdx.x;
    if (e >= E) return;
    int2 sd = edges[e];
    const float4* zp = (const float4*)&g_z[sd.x * HH];
    float4 a = zp[0];
    float4 b = zp[1];
    float* ap = &g_acc[sd.y * HH];
    atomicAdd(ap + 0, a.x); atomicAdd(ap + 1, a.y);
    atomicAdd(ap + 2, a.z); atomicAdd(ap + 3, a.w);
    atomicAdd(ap + 4, b.x); atomicAdd(ap + 5, b.y);
    atomicAdd(ap + 6, b.z); atomicAdd(ap + 7, b.w);
}

// ---------------- per-node warp-reduced BN-stats helper ----------------
__device__ __forceinline__ void stats_reduce(const float out[HH], int layer, int tid) {
#pragma unroll
    for (int h = 0; h < HH; h++) {
        float s = out[h];
        float q = out[h] * out[h];
#pragma unroll
        for (int o = 16; o; o >>= 1) {
            s += __shfl_down_sync(0xffffffffu, s, o);
            q += __shfl_down_sync(0xffffffffu, q, o);
        }
        if ((tid & 31) == 0) {
            atomicAdd(&g_stats[layer * 16 + h], (double)s);
            atomicAdd(&g_stats[layer * 16 + 8 + h], (double)q);
        }
    }
}

// ---------------- node kernel, layer 1 (root term from x, F=5) ----------------
__global__ void k_node_first(const float* __restrict__ x, const float* __restrict__ W1r) {
    __shared__ float w[HH * FIN];
    if (threadIdx.x < HH * FIN) w[threadIdx.x] = W1r[threadIdx.x];
    __syncthreads();
    int i = blockIdx.x * blockDim.x + threadIdx.x;
    bool act = i < NN;
    float out[HH];
#pragma unroll
    for (int h = 0; h < HH; h++) out[h] = 0.f;
    if (act) {
        float inv = 1.f / fmaxf(g_cntc[i], 1.f);
        float xv[FIN];
#pragma unroll
        for (int f = 0; f < FIN; f++) xv[f] = x[i * FIN + f];
#pragma unroll
        for (int h = 0; h < HH; h++) {
            float s = g_acc[i * HH + h] * inv;
#pragma unroll
            for (int f = 0; f < FIN; f++) s += xv[f] * w[h * FIN + f];
            out[h] = s;
        }
        float nrm = 0.f;
#pragma unroll
        for (int h = 0; h < HH; h++) nrm += out[h] * out[h];
        float invn = 1.f / fmaxf(sqrtf(nrm), L2_EPS);
#pragma unroll
        for (int h = 0; h < HH; h++) {
            float v = fmaxf(out[h] * invn, 0.f);
            out[h] = v;
            g_y[i * HH + h] = v;
            g_acc[i * HH + h] = 0.f;  // reset for next layer's scatter
        }
    }
    stats_reduce(out, 0, threadIdx.x);
}

// ---------------- node kernel, layers 2..5 (root term from g_h, F=8) ----------------
__global__ void k_node(const float* __restrict__ Wr, const float* __restrict__ cnt, int layer) {
    __shared__ float w[HH * HH];
    if (threadIdx.x < HH * HH) w[threadIdx.x] = Wr[threadIdx.x];
    __syncthreads();
    int i = blockIdx.x * blockDim.x + threadIdx.x;
    bool act = i < NN;
    float out[HH];
#pragma unroll
    for (int h = 0; h < HH; h++) out[h] = 0.f;
    if (act) {
        float inv = 1.f / fmaxf(cnt[i], 1.f);
        float hv[HH];
#pragma unroll
        for (int f = 0; f < HH; f++) hv[f] = g_h[i * HH + f];
#pragma unroll
        for (int h = 0; h < HH; h++) {
            float s = g_acc[i * HH + h] * inv;
#pragma unroll
            for (int f = 0; f < HH; f++) s += hv[f] * w[h * HH + f];
            out[h] = s;
        }
        float nrm = 0.f;
#pragma unroll
        for (int h = 0; h < HH; h++) nrm += out[h] * out[h];
        float invn = 1.f / fmaxf(sqrtf(nrm), L2_EPS);
#pragma unroll
        for (int h = 0; h < HH; h++) {
            float v = fmaxf(out[h] * invn, 0.f);
            out[h] = v;
            g_y[i * HH + h] = v;
            g_acc[i * HH + h] = 0.f;
        }
    }
    stats_reduce(out, layer, threadIdx.x);
}

// ---------------- BN apply (+ optionally compute next layer's z) ----------------
__global__ void k_bn(int layer, const float* __restrict__ gam, const float* __restrict__ bet,
                     const float* __restrict__ Wlnext, float* __restrict__ outp, int writeZ) {
    __shared__ float sm[HH], srs[HH], sg[HH], sb[HH], wl[HH * HH];
    int t = threadIdx.x;
    if (t < HH) {
        double s = g_stats[layer * 16 + t];
        double q = g_stats[layer * 16 + 8 + t];
        double m = s / (double)NN;
        double v = q / (double)NN - m * m;
        sm[t] = (float)m;
        srs[t] = (float)rsqrt(v + BN_EPS);
        sg[t] = gam[t];
        sb[t] = bet[t];
    }
    if (writeZ && t < HH * HH) wl[t] = Wlnext[t];
    __syncthreads();
    int i = blockIdx.x * blockDim.x + threadIdx.x;
    if (i >= NN) return;
    float hv[HH];
#pragma unroll
    for (int h = 0; h < HH; h++) {
        float v = (g_y[i * HH + h] - sm[h]) * srs[h] * sg[h] + sb[h];
        hv[h] = v;
        outp[i * HH + h] = v;
    }
    if (writeZ) {
#pragma unroll
        for (int h = 0; h < HH; h++) {
            float s = 0.f;
#pragma unroll
            for (int f = 0; f < HH; f++) s += hv[f] * wl[h * HH + f];
            g_z[i * HH + h] = s;
        }
    }
}

// ---------------- host launch ----------------
extern "C" void kernel_launch(void* const* d_in, const int* in_sizes, int n_in,
                              void* d_out, int out_size) {
    const float* x   = (const float*)d_in[0];
    const void*  eic = d_in[1];
    const void*  eid = d_in[2];
    const float* W1l = (const float*)d_in[3];
    const float* W1r = (const float*)d_in[4];
    const float* W2l = (const float*)d_in[5];
    const float* W2r = (const float*)d_in[6];
    const float* W3l = (const float*)d_in[7];
    const float* W3r = (const float*)d_in[8];
    const float* W4l = (const float*)d_in[9];
    const float* W4r = (const float*)d_in[10];
    const float* g1 = (const float*)d_in[11]; const float* b1 = (const float*)d_in[12];
    const float* g2 = (const float*)d_in[13]; const float* b2 = (const float*)d_in[14];
    const float* g3 = (const float*)d_in[15]; const float* b3 = (const float*)d_in[16];
    const float* g4 = (const float*)d_in[17]; const float* b4 = (const float*)d_in[18];
    float* out = (float*)d_out;

    const int T = 256;
    const int gN  = (NN + T - 1) / T;
    const int gNH = (NN * HH + T - 1) / T;
    const int gEC = (EC + T - 1) / T;
    const int gED = (ED + T - 1) / T;

    int2*  pec = nullptr;  cudaGetSymbolAddress((void**)&pec, g_ec);
    int2*  ped = nullptr;  cudaGetSymbolAddress((void**)&ped, g_ed);
    float* pcc = nullptr;  cudaGetSymbolAddress((void**)&pcc, g_cntc);
    float* pcd = nullptr;  cudaGetSymbolAddress((void**)&pcd, g_cntd);
    float* ph  = nullptr;  cudaGetSymbolAddress((void**)&ph, g_h);

    k_init<<<gNH, T>>>();
    k_detect<<<1, 32>>>((const int*)eic);
    k_prep<<<gEC, T>>>(eic, pec, pcc, EC);
    k_prep<<<gED, T>>>(eid, ped, pcd, ED);
    k_z_first<<<gN, T>>>(x, W1l);

    // layer 1: conv1 (W1l/W1r) + bn1 ; next scatter payload uses W4l
    k_scatter<<<gEC, T>>>(pec, EC);
    k_node_first<<<gN, T>>>(x, W1r);
    k_bn<<<gN, T>>>(0, g1, b1, W4l, ph, 1);

    // layer 2: conv4 (W4l/W4r) + bn2 ; next uses W2l
    k_scatter<<<gEC, T>>>(pec, EC);
    k_node<<<gN, T>>>(W4r, pcc, 1);
    k_bn<<<gN, T>>>(1, g2, b2, W2l, ph, 1);

    // layer 3 (destination edges): conv2 (W2l/W2r) + bn3 ; next uses W3l
    k_scatter<<<gED, T>>>(ped, ED);
    k_node<<<gN, T>>>(W2r, pcd, 2);
    k_bn<<<gN, T>>>(2, g3, b3, W3l, ph, 1);

    // layer 4: conv3 (W3l/W3r) + bn4 ; next uses W3l again
    k_scatter<<<gEC, T>>>(pec, EC);
    k_node<<<gN, T>>>(W3r, pcc, 3);
    k_bn<<<gN, T>>>(3, g4, b4, W3l, ph, 1);

    // layer 5: conv3 + bn4 again, final output -> d_out
    k_scatter<<<gEC, T>>>(pec, EC);
    k_node<<<gN, T>>>(W3r, pcc, 4);
    k_bn<<<gN, T>>>(4, g4, b4, nullptr, out, 0);
}

// round 2
// speedup vs baseline: 2.5754x; 2.5754x over previous
#include <cuda_runtime.h>
#include <cuda_fp16.h>

#define NN 100000
#define EC 6400000
#define ED 400000
#define HH 8
#define FIN 5
#define BN_EPS 1e-5
#define L2_EPS 1e-12f
#define SB 512

// ---------------- scratch ----------------
__device__ int   g_rankc[EC];
__device__ int   g_rankd[ED];
__device__ int   g_csrc[EC];                 // CSR src lists (by dst)
__device__ int   g_csrd[ED];
__device__ int   g_cntc[NN];
__device__ int   g_cntd[NN];
__device__ int   g_rowc[NN];                 // exclusive row starts
__device__ int   g_rowd[NN];
__device__ int   g_bsum[256];
__device__ __align__(16) __half g_zh[NN * HH];   // fp16 scatter payload (next Wl @ h)
__device__ __align__(16) float  g_h[NN * HH];    // post-BN features
__device__ __align__(16) float  g_y[NN * HH];    // pre-BN activations
__device__ double g_stats[5 * 16];
__device__ int    g_mode;

// ---------------- init ----------------
__global__ void k_init() {
    int i = blockIdx.x * blockDim.x + threadIdx.x;
    if (i < NN) { g_cntc[i] = 0; g_cntd[i] = 0; }
    if (i < 5 * 16) g_stats[i] = 0.0;
}

// ---------------- int64 vs int32 edge dtype detection ----------------
__global__ void k_detect(const int* __restrict__ ei) {
    int lane = threadIdx.x;
    int v = ei[2 * lane + 1];
    unsigned ball = __ballot_sync(0xffffffffu, v == 0);
    if (lane == 0) g_mode = (ball == 0xffffffffu) ? 1 : 0;
}

__device__ __forceinline__ void load_edge(const void* ei, int E, int e, int& src, int& dst) {
    if (g_mode) {
        const long long* p = (const long long*)ei;
        src = (int)p[e]; dst = (int)p[E + e];
    } else {
        const int* p = (const int*)ei;
        src = p[e]; dst = p[E + e];
    }
}

// ---------------- count + rank ----------------
__global__ void k_count(const void* __restrict__ ei, int* __restrict__ cnt,
                        int* __restrict__ rank, int E) {
    int e = blockIdx.x * blockDim.x + threadIdx.x;
    if (e >= E) return;
    int src, dst; load_edge(ei, E, e, src, dst);
    rank[e] = atomicAdd(&cnt[dst], 1);
}

// ---------------- exclusive scan over NN counts ----------------
__global__ void k_scan1(const int* __restrict__ cnt, int* __restrict__ row,
                        int* __restrict__ bsum, int n) {
    __shared__ int sh[SB];
    int tid = threadIdx.x;
    int g = blockIdx.x * SB + tid;
    int v = (g < n) ? cnt[g] : 0;
    sh[tid] = v; __syncthreads();
#pragma unroll
    for (int o = 1; o < SB; o <<= 1) {
        int t = (tid >= o) ? sh[tid - o] : 0;
        __syncthreads();
        sh[tid] += t;
        __syncthreads();
    }
    if (g < n) row[g] = sh[tid] - v;          // exclusive
    if (tid == SB - 1) bsum[blockIdx.x] = sh[SB - 1];
}
__global__ void k_scan2(int* __restrict__ bsum, int nb) {
    __shared__ int sh[256];
    int tid = threadIdx.x;
    int v = (tid < nb) ? bsum[tid] : 0;
    sh[tid] = v; __syncthreads();
#pragma unroll
    for (int o = 1; o < 256; o <<= 1) {
        int t = (tid >= o) ? sh[tid - o] : 0;
        __syncthreads();
        sh[tid] += t;
        __syncthreads();
    }
    if (tid < nb) bsum[tid] = sh[tid] - v;    // exclusive
}
__global__ void k_scan3(int* __restrict__ row, const int* __restrict__ bsum, int n) {
    int g = blockIdx.x * SB + threadIdx.x;
    if (g < n) row[g] += bsum[blockIdx.x];
}

// ---------------- CSR placement ----------------
__global__ void k_place(const void* __restrict__ ei, const int* __restrict__ rank,
                        const int* __restrict__ row, int* __restrict__ csr, int E) {
    int e = blockIdx.x * blockDim.x + threadIdx.x;
    if (e >= E) return;
    int src, dst; load_edge(ei, E, e, src, dst);
    csr[row[dst] + rank[e]] = src;
}

// ---------------- z for layer 1: z = x @ W1l^T (fp16 out) ----------------
__global__ void k_z_first(const float* __restrict__ x, const float* __restrict__ W1l) {
    __shared__ float w[HH * FIN];
    if (threadIdx.x < HH * FIN) w[threadIdx.x] = W1l[threadIdx.x];
    __syncthreads();
    int i = blockIdx.x * blockDim.x + threadIdx.x;
    if (i >= NN) return;
    float xv[FIN];
#pragma unroll
    for (int f = 0; f < FIN; f++) xv[f] = x[i * FIN + f];
    float z[HH];
#pragma unroll
    for (int h = 0; h < HH; h++) {
        float s = 0.f;
#pragma unroll
        for (int f = 0; f < FIN; f++) s += xv[f] * w[h * FIN + f];
        z[h] = s;
    }
    __half2 out[4];
#pragma unroll
    for (int k = 0; k < 4; k++) out[k] = __floats2half2_rn(z[2 * k], z[2 * k + 1]);
    *(uint4*)&g_zh[i * HH] = *(uint4*)out;
}

// ---------------- gather acc = sum_{src in row} z[src] ----------------
__device__ __forceinline__ void gather_row(int s, int d, const int* __restrict__ csr,
                                           float acc[HH]) {
    int e = s + d;
    int p = s;
    for (; p + 1 < e; p += 2) {
        int s0 = __ldg(&csr[p]);
        int s1 = __ldg(&csr[p + 1]);
        uint4 a = *(const uint4*)&g_zh[s0 * HH];
        uint4 b = *(const uint4*)&g_zh[s1 * HH];
        const __half2* ah = (const __half2*)&a;
        const __half2* bh = (const __half2*)&b;
#pragma unroll
        for (int k = 0; k < 4; k++) {
            float2 fa = __half22float2(ah[k]);
            float2 fb = __half22float2(bh[k]);
            acc[2 * k]     += fa.x + fb.x;
            acc[2 * k + 1] += fa.y + fb.y;
        }
    }
    if (p < e) {
        int s0 = __ldg(&csr[p]);
        uint4 a = *(const uint4*)&g_zh[s0 * HH];
        const __half2* ah = (const __half2*)&a;
#pragma unroll
        for (int k = 0; k < 4; k++) {
            float2 fa = __half22float2(ah[k]);
            acc[2 * k]     += fa.x;
            acc[2 * k + 1] += fa.y;
        }
    }
}

__device__ __forceinline__ void stats_reduce(const float out[HH], int layer, int tid) {
#pragma unroll
    for (int h = 0; h < HH; h++) {
        float s = out[h];
        float q = out[h] * out[h];
#pragma unroll
        for (int o = 16; o; o >>= 1) {
            s += __shfl_down_sync(0xffffffffu, s, o);
            q += __shfl_down_sync(0xffffffffu, q, o);
        }
        if ((tid & 31) == 0) {
            atomicAdd(&g_stats[layer * 16 + h], (double)s);
            atomicAdd(&g_stats[layer * 16 + 8 + h], (double)q);
        }
    }
}

__device__ __forceinline__ void finish_node(float out[HH], int i, int layer, int tid) {
    float nrm = 0.f;
#pragma unroll
    for (int h = 0; h < HH; h++) nrm += out[h] * out[h];
    float invn = 1.f / fmaxf(sqrtf(nrm), L2_EPS);
#pragma unroll
    for (int h = 0; h < HH; h++) {
        float v = fmaxf(out[h] * invn, 0.f);
        out[h] = v;
        g_y[i * HH + h] = v;
    }
}

// ---------------- layer 1: gather + node (root from x, F=5) ----------------
__global__ void k_layer_first(const float* __restrict__ x, const float* __restrict__ W1r) {
    __shared__ float w[HH * FIN];
    if (threadIdx.x < HH * FIN) w[threadIdx.x] = W1r[threadIdx.x];
    __syncthreads();
    int i = blockIdx.x * blockDim.x + threadIdx.x;
    bool act = i < NN;
    float out[HH];
#pragma unroll
    for (int h = 0; h < HH; h++) out[h] = 0.f;
    if (act) {
        int s = g_rowc[i], d = g_cntc[i];
        float acc[HH];
#pragma unroll
        for (int h = 0; h < HH; h++) acc[h] = 0.f;
        gather_row(s, d, g_csrc, acc);
        float inv = 1.f / fmaxf((float)d, 1.f);
        float xv[FIN];
#pragma unroll
        for (int f = 0; f < FIN; f++) xv[f] = x[i * FIN + f];
#pragma unroll
        for (int h = 0; h < HH; h++) {
            float sum = acc[h] * inv;
#pragma unroll
            for (int f = 0; f < FIN; f++) sum += xv[f] * w[h * FIN + f];
            out[h] = sum;
        }
        finish_node(out, i, 0, threadIdx.x);
    }
    stats_reduce(out, 0, threadIdx.x);
}

// ---------------- layers 2..5: gather + node (root from g_h) ----------------
__global__ void k_layer(const int* __restrict__ row, const int* __restrict__ cnt,
                        const int* __restrict__ csr, const float* __restrict__ Wr, int layer) {
    __shared__ float w[HH * HH];
    if (threadIdx.x < HH * HH) w[threadIdx.x] = Wr[threadIdx.x];
    __syncthreads();
    int i = blockIdx.x * blockDim.x + threadIdx.x;
    bool act = i < NN;
    float out[HH];
#pragma unroll
    for (int h = 0; h < HH; h++) out[h] = 0.f;
    if (act) {
        int s = row[i], d = cnt[i];
        float acc[HH];
#pragma unroll
        for (int h = 0; h < HH; h++) acc[h] = 0.f;
        gather_row(s, d, csr, acc);
        float inv = 1.f / fmaxf((float)d, 1.f);
        float hv[HH];
#pragma unroll
        for (int f = 0; f < HH; f++) hv[f] = g_h[i * HH + f];
#pragma unroll
        for (int h = 0; h < HH; h++) {
            float sum = acc[h] * inv;
#pragma unroll
            for (int f = 0; f < HH; f++) sum += hv[f] * w[h * HH + f];
            out[h] = sum;
        }
        finish_node(out, i, layer, threadIdx.x);
    }
    stats_reduce(out, layer, threadIdx.x);
}

// ---------------- BN apply + next-layer z (fp16) ----------------
__global__ void k_bn(int layer, const float* __restrict__ gam, const float* __restrict__ bet,
                     const float* __restrict__ Wlnext, float* __restrict__ outp, int writeZ) {
    __shared__ float sm[HH], srs[HH], sg[HH], sb[HH], wl[HH * HH];
    int t = threadIdx.x;
    if (t < HH) {
        double s = g_stats[layer * 16 + t];
        double q = g_stats[layer * 16 + 8 + t];
        double m = s / (double)NN;
        double v = q / (double)NN - m * m;
        sm[t] = (float)m;
        srs[t] = (float)rsqrt(v + BN_EPS);
        sg[t] = gam[t];
        sb[t] = bet[t];
    }
    if (writeZ && t < HH * HH) wl[t] = Wlnext[t];
    __syncthreads();
    int i = blockIdx.x * blockDim.x + threadIdx.x;
    if (i >= NN) return;
    float hv[HH];
#pragma unroll
    for (int h = 0; h < HH; h++) {
        float v = (g_y[i * HH + h] - sm[h]) * srs[h] * sg[h] + sb[h];
        hv[h] = v;
        outp[i * HH + h] = v;
    }
    if (writeZ) {
        float z[HH];
#pragma unroll
        for (int h = 0; h < HH; h++) {
            float s = 0.f;
#pragma unroll
            for (int f = 0; f < HH; f++) s += hv[f] * wl[h * HH + f];
            z[h] = s;
        }
        __half2 zo[4];
#pragma unroll
        for (int k = 0; k < 4; k++) zo[k] = __floats2half2_rn(z[2 * k], z[2 * k + 1]);
        *(uint4*)&g_zh[i * HH] = *(uint4*)zo;
    }
}

// ---------------- host ----------------
extern "C" void kernel_launch(void* const* d_in, const int* in_sizes, int n_in,
                              void* d_out, int out_size) {
    const float* x   = (const float*)d_in[0];
    const void*  eic = d_in[1];
    const void*  eid = d_in[2];
    const float* W1l = (const float*)d_in[3];
    const float* W1r = (const float*)d_in[4];
    const float* W2l = (const float*)d_in[5];
    const float* W2r = (const float*)d_in[6];
    const float* W3l = (const float*)d_in[7];
    const float* W3r = (const float*)d_in[8];
    const float* W4l = (const float*)d_in[9];
    const float* W4r = (const float*)d_in[10];
    const float* g1 = (const float*)d_in[11]; const float* b1 = (const float*)d_in[12];
    const float* g2 = (const float*)d_in[13]; const float* b2 = (const float*)d_in[14];
    const float* g3 = (const float*)d_in[15]; const float* b3 = (const float*)d_in[16];
    const float* g4 = (const float*)d_in[17]; const float* b4 = (const float*)d_in[18];
    float* out = (float*)d_out;

    const int T = 256;
    const int gN  = (NN + T - 1) / T;
    const int gEC = (EC + T - 1) / T;
    const int gED = (ED + T - 1) / T;
    const int nbN = (NN + SB - 1) / SB;

    int* prankc; cudaGetSymbolAddress((void**)&prankc, g_rankc);
    int* prankd; cudaGetSymbolAddress((void**)&prankd, g_rankd);
    int* pcsrc;  cudaGetSymbolAddress((void**)&pcsrc, g_csrc);
    int* pcsrd;  cudaGetSymbolAddress((void**)&pcsrd, g_csrd);
    int* pcc;    cudaGetSymbolAddress((void**)&pcc, g_cntc);
    int* pcd;    cudaGetSymbolAddress((void**)&pcd, g_cntd);
    int* prc;    cudaGetSymbolAddress((void**)&prc, g_rowc);
    int* prd;    cudaGetSymbolAddress((void**)&prd, g_rowd);
    int* pbs;    cudaGetSymbolAddress((void**)&pbs, g_bsum);
    float* ph;   cudaGetSymbolAddress((void**)&ph, g_h);

    // ---- CSR build ----
    k_init<<<gN, T>>>();
    k_detect<<<1, 32>>>((const int*)eic);
    k_count<<<gEC, T>>>(eic, pcc, prankc, EC);
    k_count<<<gED, T>>>(eid, pcd, prankd, ED);
    k_scan1<<<nbN, SB>>>(pcc, prc, pbs, NN);
    k_scan2<<<1, 256>>>(pbs, nbN);
    k_scan3<<<nbN, SB>>>(prc, pbs, NN);
    k_scan1<<<nbN, SB>>>(pcd, prd, pbs, NN);
    k_scan2<<<1, 256>>>(pbs, nbN);
    k_scan3<<<nbN, SB>>>(prd, pbs, NN);
    k_place<<<gEC, T>>>(eic, prankc, prc, pcsrc, EC);
    k_place<<<gED, T>>>(eid, prankd, prd, pcsrd, ED);
    k_z_first<<<gN, T>>>(x, W1l);

    // ---- layer 1: conv1 + bn1 (next payload W4l) ----
    k_layer_first<<<gN, T>>>(x, W1r);
    k_bn<<<gN, T>>>(0, g1, b1, W4l, ph, 1);
    // ---- layer 2: conv4 + bn2 (next W2l) ----
    k_layer<<<gN, T>>>(prc, pcc, pcsrc, W4r, 1);
    k_bn<<<gN, T>>>(1, g2, b2, W2l, ph, 1);
    // ---- layer 3 (destination edges): conv2 + bn3 (next W3l) ----
    k_layer<<<gN, T>>>(prd, pcd, pcsrd, W2r, 2);
    k_bn<<<gN, T>>>(2, g3, b3, W3l, ph, 1);
    // ---- layer 4: conv3 + bn4 (next W3l) ----
    k_layer<<<gN, T>>>(prc, pcc, pcsrc, W3r, 3);
    k_bn<<<gN, T>>>(3, g4, b4, W3l, ph, 1);
    // ---- layer 5: conv3 + bn4 -> d_out ----
    k_layer<<<gN, T>>>(prc, pcc, pcsrc, W3r, 4);
    k_bn<<<gN, T>>>(4, g4, b4, nullptr, out, 0);
}